// round 17
// baseline (speedup 1.0000x reference)
#include <cuda_runtime.h>
#include <math.h>

// ---------------- problem constants ----------------
#define NU 100000
#define NM 20000
#define FU 32
#define FM 128
#define H1 8
#define C1 16
#define D1 128
#define H2 4
#define C2 128
#define D2 512
#define NE 250000
#define NEL 200000
#define NTOT (NM + NU)   // combined CSR buckets: um dsts [0,NM), mu dsts [NM,NTOT)

// ---------------- device scratch ----------------
__device__ float g_zu1  [(size_t)NU * D1];
__device__ float g_zm1  [(size_t)NM * D1];
__device__ float g_hsmu1[(size_t)NM * D1];     // xm @ w1mu_s
__device__ float g_Pu   [(size_t)NU * 128];    // zu1 @ Bu  (cols 0-63 proj, 64-71 scores)
__device__ float g_Pm   [(size_t)NM * 128];    // zm1 @ Bm
__device__ float g_s1u  [NU * 16];             // xu scores: 0-7 um_src, 8-15 mu_dst
__device__ float g_s1m  [NM * 16];             // xm scores: 0-7 mu_src, 8-15 um_dst
__device__ float g_preu [(size_t)NU * 16];
__device__ float g_prem [(size_t)NM * 16];
__device__ float g_Qu[32 * 16];
__device__ float g_Qm[128 * 16];
__device__ float g_Bu[128 * 128];
__device__ float g_Bm[128 * 128];
__device__ float g_cm[16];
__device__ float g_cu[16];
__device__ int g_row [NTOT];
__device__ int g_cur [NTOT];
__device__ int g_ssrc[2 * NE];
__device__ int g_bsum[128];

__device__ __forceinline__ unsigned f2tf(float x) {
    unsigned u;
    asm("cvt.rna.tf32.f32 %0, %1;" : "=r"(u) : "f"(x));
    return u;
}

// ================= TF32 dual GEMM: C[M,128] = A[M,128] @ B[128,128] =================
#define TBM 128
#define TBK 16
#define TPAD 4

struct GP { const float* A; const float* B; float* C; int M; };

__global__ void __launch_bounds__(256, 2)
gemm_dual(GP p0, GP p1) {
    const GP p = (blockIdx.z == 0) ? p0 : p1;
    const int row0 = blockIdx.y * TBM;
    if (row0 >= p.M) return;

    __shared__ unsigned As[2][TBK][TBM + TPAD];
    __shared__ unsigned Bs[2][TBK][128 + TPAD];

    const float* __restrict__ A = p.A;
    const float* __restrict__ B = p.B;
    const int M = p.M;
    const int K = 128, N = 128;

    const int tid  = threadIdx.x;
    const int lane = tid & 31;
    const int wid  = tid >> 5;
    const int wm0  = (wid & 1) * 64;
    const int wn0  = (wid >> 1) * 32;
    const int lr   = lane >> 2;
    const int lc   = lane & 3;

    float acc[4][4][4];
#pragma unroll
    for (int mt = 0; mt < 4; mt++)
#pragma unroll
        for (int nt = 0; nt < 4; nt++)
#pragma unroll
            for (int q = 0; q < 4; q++) acc[mt][nt][q] = 0.f;

    float4 aR[2], bR[2];
    const int nkt = K / TBK;   // 8

#pragma unroll
    for (int it = 0; it < 2; it++) {
        int idx = tid + it * 256;
        int r = idx >> 2, kq = (idx & 3) * 4;
        int gr = row0 + r;
        aR[it] = make_float4(0.f, 0.f, 0.f, 0.f);
        if (gr < M) aR[it] = *(const float4*)(A + (size_t)gr * K + kq);
        int k = idx >> 5, cq = (idx & 31) * 4;
        bR[it] = *(const float4*)(B + (size_t)k * N + cq);
    }
#pragma unroll
    for (int it = 0; it < 2; it++) {
        int idx = tid + it * 256;
        int r = idx >> 2, kq = (idx & 3) * 4;
        As[0][kq + 0][r] = f2tf(aR[it].x);
        As[0][kq + 1][r] = f2tf(aR[it].y);
        As[0][kq + 2][r] = f2tf(aR[it].z);
        As[0][kq + 3][r] = f2tf(aR[it].w);
        int k = idx >> 5, cq = (idx & 31) * 4;
        Bs[0][k][cq + 0] = f2tf(bR[it].x);
        Bs[0][k][cq + 1] = f2tf(bR[it].y);
        Bs[0][k][cq + 2] = f2tf(bR[it].z);
        Bs[0][k][cq + 3] = f2tf(bR[it].w);
    }
    __syncthreads();

    for (int t = 0; t < nkt; t++) {
        if (t + 1 < nkt) {
            int k0 = (t + 1) * TBK;
#pragma unroll
            for (int it = 0; it < 2; it++) {
                int idx = tid + it * 256;
                int r = idx >> 2, kq = (idx & 3) * 4;
                int gr = row0 + r;
                aR[it] = make_float4(0.f, 0.f, 0.f, 0.f);
                if (gr < M) aR[it] = *(const float4*)(A + (size_t)gr * K + k0 + kq);
                int k = idx >> 5, cq = (idx & 31) * 4;
                bR[it] = *(const float4*)(B + (size_t)(k0 + k) * N + cq);
            }
        }
        const int buf = t & 1;
#pragma unroll
        for (int ks = 0; ks < TBK; ks += 8) {
            unsigned af[4][4], bf[4][2];
#pragma unroll
            for (int mt = 0; mt < 4; mt++) {
                int r = wm0 + mt * 16 + lr;
                int c = ks + lc;
                af[mt][0] = As[buf][c][r];
                af[mt][1] = As[buf][c][r + 8];
                af[mt][2] = As[buf][c + 4][r];
                af[mt][3] = As[buf][c + 4][r + 8];
            }
#pragma unroll
            for (int nt = 0; nt < 4; nt++) {
                int n = wn0 + nt * 8 + lr;
                int k = ks + lc;
                bf[nt][0] = Bs[buf][k][n];
                bf[nt][1] = Bs[buf][k + 4][n];
            }
#pragma unroll
            for (int mt = 0; mt < 4; mt++)
#pragma unroll
                for (int nt = 0; nt < 4; nt++) {
                    float* d = acc[mt][nt];
                    asm volatile(
                        "mma.sync.aligned.m16n8k8.row.col.f32.tf32.tf32.f32 "
                        "{%0,%1,%2,%3}, {%4,%5,%6,%7}, {%8,%9}, {%0,%1,%2,%3};\n"
                        : "+f"(d[0]), "+f"(d[1]), "+f"(d[2]), "+f"(d[3])
                        : "r"(af[mt][0]), "r"(af[mt][1]), "r"(af[mt][2]), "r"(af[mt][3]),
                          "r"(bf[nt][0]), "r"(bf[nt][1]));
                }
        }
        if (t + 1 < nkt) {
            const int nb = buf ^ 1;
#pragma unroll
            for (int it = 0; it < 2; it++) {
                int idx = tid + it * 256;
                int r = idx >> 2, kq = (idx & 3) * 4;
                As[nb][kq + 0][r] = f2tf(aR[it].x);
                As[nb][kq + 1][r] = f2tf(aR[it].y);
                As[nb][kq + 2][r] = f2tf(aR[it].z);
                As[nb][kq + 3][r] = f2tf(aR[it].w);
                int k = idx >> 5, cq = (idx & 31) * 4;
                Bs[nb][k][cq + 0] = f2tf(bR[it].x);
                Bs[nb][k][cq + 1] = f2tf(bR[it].y);
                Bs[nb][k][cq + 2] = f2tf(bR[it].z);
                Bs[nb][k][cq + 3] = f2tf(bR[it].w);
            }
            __syncthreads();
        }
    }
    float* C = p.C;
#pragma unroll
    for (int mt = 0; mt < 4; mt++) {
#pragma unroll
        for (int half = 0; half < 2; half++) {
            int gr = row0 + wm0 + mt * 16 + lr + half * 8;
            if (gr < M) {
#pragma unroll
                for (int nt = 0; nt < 4; nt++) {
                    float2 v = half ? make_float2(acc[mt][nt][2], acc[mt][nt][3])
                                    : make_float2(acc[mt][nt][0], acc[mt][nt][1]);
                    *(float2*)(C + (size_t)gr * 128 + wn0 + nt * 8 + lc * 2) = v;
                }
            }
        }
    }
}

// ================= merged compose kernel (fp32, tiny) =================
__global__ void compose_all(const float* __restrict__ w1um_s, const float* __restrict__ a1um_s,
                            const float* __restrict__ w1mu_d, const float* __restrict__ a1mu_d,
                            const float* __restrict__ w1mu_s, const float* __restrict__ a1mu_s,
                            const float* __restrict__ w1um_d, const float* __restrict__ a1um_d,
                            const float* __restrict__ w2um_s, const float* __restrict__ a2um_s,
                            const float* __restrict__ w2mu_d, const float* __restrict__ a2mu_d,
                            const float* __restrict__ w2mu_s, const float* __restrict__ a2mu_s,
                            const float* __restrict__ w2um_d, const float* __restrict__ a2um_d,
                            const float* __restrict__ dw1,
                            const float* __restrict__ b2um, const float* __restrict__ b2mu,
                            float* __restrict__ Qu, float* __restrict__ Qm,
                            float* __restrict__ Bu, float* __restrict__ Bm,
                            float* __restrict__ cm, float* __restrict__ cu) {
    int t = blockIdx.x * blockDim.x + threadIdx.x;
    if (t < 512) {
        int k = t >> 4, j = t & 15, h = j & 7;
        const float* W = (j < 8) ? w1um_s : w1mu_d;
        const float* a = (j < 8) ? a1um_s : a1mu_d;
        float acc = 0.f;
        for (int c = 0; c < 16; c++) acc += W[k * 128 + h * 16 + c] * a[h * 16 + c];
        Qu[t] = acc;
    } else if (t < 2560) {
        int tt = t - 512;
        int k = tt >> 4, j = tt & 15, h = j & 7;
        const float* W = (j < 8) ? w1mu_s : w1um_d;
        const float* a = (j < 8) ? a1mu_s : a1um_d;
        float acc = 0.f;
        for (int c = 0; c < 16; c++) acc += W[k * 128 + h * 16 + c] * a[h * 16 + c];
        Qm[tt] = acc;
    } else if (t < 2560 + 32768) {
        int tb = t - 2560;
        int which = tb >> 14;
        int tt = tb & 16383;
        int k = tt >> 7, j = tt & 127;
        float acc = 0.f;
        if (which == 0) {
            if (j < 64) {
                int h = j >> 4, jj = j & 15;
                for (int i = 0; i < 128; i++)
                    acc += w2um_s[k * 512 + h * 128 + i] * dw1[(size_t)(512 + h * 128 + i) * 16 + jj];
            } else if (j < 68) {
                int h = j - 64;
                for (int c = 0; c < 128; c++) acc += w2um_s[k * 512 + h * 128 + c] * a2um_s[h * 128 + c];
            } else if (j < 72) {
                int h = j - 68;
                for (int c = 0; c < 128; c++) acc += w2mu_d[k * 512 + h * 128 + c] * a2mu_d[h * 128 + c];
            }
            Bu[tt] = acc;
        } else {
            if (j < 64) {
                int h = j >> 4, jj = j & 15;
                for (int i = 0; i < 128; i++)
                    acc += w2mu_s[k * 512 + h * 128 + i] * dw1[(size_t)(h * 128 + i) * 16 + jj];
            } else if (j < 68) {
                int h = j - 64;
                for (int c = 0; c < 128; c++) acc += w2mu_s[k * 512 + h * 128 + c] * a2mu_s[h * 128 + c];
            } else if (j < 72) {
                int h = j - 68;
                for (int c = 0; c < 128; c++) acc += w2um_d[k * 512 + h * 128 + c] * a2um_d[h * 128 + c];
            }
            Bm[tt] = acc;
        }
    } else if (t < 2560 + 32768 + 32) {
        int j = t - (2560 + 32768);
        if (j < 16) {
            float acc = 0.f;
            for (int i = 0; i < 512; i++) acc += b2um[i] * dw1[(size_t)(512 + i) * 16 + j];
            cm[j] = acc;
        } else {
            int jj = j - 16;
            float acc = 0.f;
            for (int i = 0; i < 512; i++) acc += b2mu[i] * dw1[(size_t)i * 16 + jj];
            cu[jj] = acc;
        }
    }
}

// ================= merged node scores: warp-per-node, both node types =================
template <int K>
__device__ __forceinline__ void score_node(const float* __restrict__ xr,
                                           const float* __restrict__ Q,
                                           float* __restrict__ sp_out, int lane) {
    float p[16];
#pragma unroll
    for (int j = 0; j < 16; j++) p[j] = 0.f;
#pragma unroll
    for (int kk = 0; kk < K / 32; kk++) {
        int k = kk * 32 + lane;
        float xv = xr[k];
        const float4* q4 = (const float4*)(Q + k * 16);
        float4 q0 = q4[0], q1 = q4[1], q2 = q4[2], q3 = q4[3];
        p[0] += xv * q0.x; p[1] += xv * q0.y; p[2]  += xv * q0.z; p[3]  += xv * q0.w;
        p[4] += xv * q1.x; p[5] += xv * q1.y; p[6]  += xv * q1.z; p[7]  += xv * q1.w;
        p[8] += xv * q2.x; p[9] += xv * q2.y; p[10] += xv * q2.z; p[11] += xv * q2.w;
        p[12]+= xv * q3.x; p[13]+= xv * q3.y; p[14] += xv * q3.z; p[15] += xv * q3.w;
    }
#pragma unroll
    for (int j = 0; j < 16; j++)
#pragma unroll
        for (int o = 16; o; o >>= 1) p[j] += __shfl_xor_sync(0xffffffffu, p[j], o);
    if (lane == 0) {
        float4* sp = (float4*)sp_out;
        sp[0] = make_float4(p[0], p[1], p[2], p[3]);
        sp[1] = make_float4(p[4], p[5], p[6], p[7]);
        sp[2] = make_float4(p[8], p[9], p[10], p[11]);
        sp[3] = make_float4(p[12], p[13], p[14], p[15]);
    }
}

__global__ void score_both(const float* __restrict__ xu, const float* __restrict__ Qu,
                           float* __restrict__ s1u,
                           const float* __restrict__ xm, const float* __restrict__ Qm,
                           float* __restrict__ s1m) {
    int warp = (blockIdx.x * blockDim.x + threadIdx.x) >> 5;
    int lane = threadIdx.x & 31;
    if (warp < NU) {
        score_node<32>(xu + (size_t)warp * 32, Qu, s1u + (size_t)warp * 16, lane);
    } else if (warp < NU + NM) {
        int n = warp - NU;
        score_node<128>(xm + (size_t)n * 128, Qm, s1m + (size_t)n * 16, lane);
    }
}

// ================= CSR build (add_off folded away; consumers add bsum[d>>10]) ========
__global__ void zero_int(int* __restrict__ p, int n) {
    int i = blockIdx.x * blockDim.x + threadIdx.x;
    if (i < n) p[i] = 0;
}
__global__ void count2_k(const int* __restrict__ um_dst, const int* __restrict__ mu_dst,
                         int* __restrict__ cnt) {
    int i = blockIdx.x * blockDim.x + threadIdx.x;
    if (i >= 2 * NE) return;
    int d = (i < NE) ? um_dst[i] : (NM + mu_dst[i - NE]);
    atomicAdd(&cnt[d], 1);
}
__global__ void scan_block(int* __restrict__ cnt, int* __restrict__ row,
                           int* __restrict__ bsum, int n) {
    __shared__ int sh[1024];
    int i = blockIdx.x * 1024 + threadIdx.x;
    int v = (i < n) ? cnt[i] : 0;
    sh[threadIdx.x] = v;
    __syncthreads();
    for (int o = 1; o < 1024; o <<= 1) {
        int t = (threadIdx.x >= o) ? sh[threadIdx.x - o] : 0;
        __syncthreads();
        sh[threadIdx.x] += t;
        __syncthreads();
    }
    if (i < n) { row[i] = sh[threadIdx.x] - v; cnt[i] = 0; }
    if (threadIdx.x == 1023) bsum[blockIdx.x] = sh[1023];
}
__global__ void scan_bsum(int* __restrict__ bsum, int nb) {
    __shared__ int sh[128];
    int t = threadIdx.x;
    int v = (t < nb) ? bsum[t] : 0;
    sh[t] = v;
    __syncthreads();
    for (int o = 1; o < 128; o <<= 1) {
        int x = (t >= o) ? sh[t - o] : 0;
        __syncthreads();
        sh[t] += x;
        __syncthreads();
    }
    if (t < nb) bsum[t] = sh[t] - v;
}
__global__ void scatter2_k(const int* __restrict__ um_src, const int* __restrict__ um_dst,
                           const int* __restrict__ mu_src, const int* __restrict__ mu_dst,
                           const int* __restrict__ row, const int* __restrict__ bsum,
                           int* __restrict__ cur, int* __restrict__ ssrc) {
    int i = blockIdx.x * blockDim.x + threadIdx.x;
    if (i >= 2 * NE) return;
    int d, s;
    if (i < NE) { d = um_dst[i]; s = um_src[i]; }
    else        { d = NM + mu_dst[i - NE]; s = mu_src[i - NE]; }
    int pos = row[d] + bsum[d >> 10] + atomicAdd(&cur[d], 1);
    ssrc[pos] = s;
}

// ================= L1 merged aggregation: um blocks [0,NM), mu blocks 2-users each ====
__global__ void __launch_bounds__(256)
agg1_both(const float* __restrict__ xu, const float* __restrict__ s1u,
          const float* __restrict__ s1m, const float* __restrict__ w1um_s,
          const float* __restrict__ b1um, float* __restrict__ zm1,
          const float* __restrict__ hs, const float* __restrict__ b1mu,
          float* __restrict__ zu1,
          const int* __restrict__ row, const int* __restrict__ deg_,
          const int* __restrict__ bsum, const int* __restrict__ ssrc) {
    int b = blockIdx.x;
    if (b < NM) {
        // ---- um path: movie dst, warp = head, lane = input feature ----
        int d = b;
        int h = threadIdx.x >> 5;
        int k = threadIdx.x & 31;
        int start = row[d] + bsum[d >> 10];
        int deg = deg_[d];
        const int* sp = ssrc + start;
        float sdd = s1m[d * 16 + 8 + h];
        float acc = 0.f, se = 0.f;
        for (int e = 0; e < deg; e++) {
            int s = sp[e];
            float v = s1u[s * 16 + h] + sdd;
            v = (v > 0.f) ? v : 0.2f * v;
            float w = __expf(v);
            se += w;
            acc += w * xu[(size_t)s * FU + k];
        }
        float agg = acc / (se + 1e-16f);
        const float4* w4 = (const float4*)(w1um_s + k * 128 + h * 16);
        float4 w0 = w4[0], w1 = w4[1], w2 = w4[2], w3 = w4[3];
        float p[16];
        p[0] = agg * w0.x; p[1] = agg * w0.y; p[2]  = agg * w0.z; p[3]  = agg * w0.w;
        p[4] = agg * w1.x; p[5] = agg * w1.y; p[6]  = agg * w1.z; p[7]  = agg * w1.w;
        p[8] = agg * w2.x; p[9] = agg * w2.y; p[10] = agg * w2.z; p[11] = agg * w2.w;
        p[12]= agg * w3.x; p[13]= agg * w3.y; p[14] = agg * w3.z; p[15] = agg * w3.w;
#pragma unroll
        for (int j = 0; j < 16; j++)
#pragma unroll
            for (int o = 16; o; o >>= 1) p[j] += __shfl_xor_sync(0xffffffffu, p[j], o);
        if (k == 0) {
            float* out = zm1 + (size_t)d * 128 + h * 16;
            const float* bb = b1um + h * 16;
#pragma unroll
            for (int j = 0; j < 16; j++) out[j] = fmaxf(p[j] + bb[j], 0.f);
        }
    } else {
        // ---- mu path: 2 user dsts per block, 128 threads each ----
        int d = (b - NM) * 2 + (threadIdx.x >> 7);   // NU even -> always valid
        int tid = threadIdx.x & 127;
        int h = tid >> 4;
        int bucket = NM + d;
        int start = row[bucket] + bsum[bucket >> 10];
        int deg = deg_[bucket];
        const int* sp = ssrc + start;
        float sdd = s1u[d * 16 + 8 + h];
        float acc = 0.f, se = 0.f;
#pragma unroll 4
        for (int e = 0; e < deg; e++) {
            int s = sp[e];
            float v = s1m[s * 16 + h] + sdd;
            v = (v > 0.f) ? v : 0.2f * v;
            float w = __expf(v);
            se += w;
            acc += w * hs[(size_t)s * 128 + tid];
        }
        zu1[(size_t)d * 128 + tid] = fmaxf(acc / (se + 1e-16f) + b1mu[tid], 0.f);
    }
}

// ================= L2: fused aggregation + decoder pre, 4 dst per 256-thread block ===
__global__ void __launch_bounds__(256)
agg2(const float* __restrict__ Pu, const float* __restrict__ Pm,
     const float* __restrict__ cm, const float* __restrict__ cu,
     float* __restrict__ prem, float* __restrict__ preu,
     const int* __restrict__ row, const int* __restrict__ deg_,
     const int* __restrict__ bsum, const int* __restrict__ ssrc) {
    __shared__ float red[4][16];
    int g = threadIdx.x >> 6;               // group 0..3
    int d = blockIdx.x * 4 + g;             // NTOT = 120000 divisible by 4
    int t = threadIdx.x & 63;
    const float *Psrc, *Pdrow, *c; float* out; int ld;
    if (d < NM) { Psrc = Pu; c = cm; out = prem; ld = d;      Pdrow = Pm + (size_t)d * 128; }
    else        { Psrc = Pm; c = cu; out = preu; ld = d - NM; Pdrow = Pu + (size_t)ld * 128; }
    int h = t >> 4, jj = t & 15;
    int start = row[d] + bsum[d >> 10];
    int deg = deg_[d];
    const int* sp = ssrc + start;
    float sdd = Pdrow[68 + h];
    float acc = 0.f, se = 0.f;
#pragma unroll 2
    for (int e = 0; e < deg; e++) {
        int s = sp[e];
        const float* pr = Psrc + (size_t)s * 128;
        float v = pr[64 + h] + sdd;
        v = (v > 0.f) ? v : 0.2f * v;
        float w = __expf(v);
        se += w;
        acc += w * pr[t];
    }
    float val = acc / (se + 1e-16f);
    if (t < 16) red[g][t] = 0.f;
    __syncthreads();
    atomicAdd(&red[g][jj], val);
    __syncthreads();
    if (t < 16) out[(size_t)ld * 16 + t] = red[g][t] + c[t];
}

// ================= decoder final =================
__global__ void dec_final(const float* __restrict__ preu, const float* __restrict__ prem,
                          const int* __restrict__ lu, const int* __restrict__ lm,
                          const float* __restrict__ db1, const float* __restrict__ dw2,
                          const float* __restrict__ db2, float* __restrict__ out, int EL) {
    int i = blockIdx.x * blockDim.x + threadIdx.x;
    if (i >= EL) return;
    const float* pu = preu + (size_t)lu[i] * 16;
    const float* pm = prem + (size_t)lm[i] * 16;
    float r = db2[0];
#pragma unroll
    for (int j = 0; j < 16; j++) {
        float h = fmaxf(pu[j] + pm[j] + db1[j], 0.f);
        r += h * dw2[j];
    }
    out[i] = r;
}

extern "C" void kernel_launch(void* const* d_in, const int* in_sizes, int n_in,
                              void* d_out, int out_size) {
    const float* xu     = (const float*)d_in[0];
    const float* xm     = (const float*)d_in[1];
    const int*   um_src = (const int*)d_in[2];
    const int*   um_dst = (const int*)d_in[3];
    const int*   mu_src = (const int*)d_in[4];
    const int*   mu_dst = (const int*)d_in[5];
    const int*   lab_u  = (const int*)d_in[6];
    const int*   lab_m  = (const int*)d_in[7];
    const float* w1um_s = (const float*)d_in[8];
    const float* w1um_d = (const float*)d_in[9];
    const float* a1um_s = (const float*)d_in[10];
    const float* a1um_d = (const float*)d_in[11];
    const float* b1um   = (const float*)d_in[12];
    const float* w1mu_s = (const float*)d_in[13];
    const float* w1mu_d = (const float*)d_in[14];
    const float* a1mu_s = (const float*)d_in[15];
    const float* a1mu_d = (const float*)d_in[16];
    const float* b1mu   = (const float*)d_in[17];
    const float* w2um_s = (const float*)d_in[18];
    const float* w2um_d = (const float*)d_in[19];
    const float* a2um_s = (const float*)d_in[20];
    const float* a2um_d = (const float*)d_in[21];
    const float* b2um   = (const float*)d_in[22];
    const float* w2mu_s = (const float*)d_in[23];
    const float* w2mu_d = (const float*)d_in[24];
    const float* a2mu_s = (const float*)d_in[25];
    const float* a2mu_d = (const float*)d_in[26];
    const float* b2mu   = (const float*)d_in[27];
    const float* dw1    = (const float*)d_in[28];
    const float* db1    = (const float*)d_in[29];
    const float* dw2    = (const float*)d_in[30];
    const float* db2    = (const float*)d_in[31];

    float *ZU1, *ZM1, *HSMU1, *PU, *PM, *S1U, *S1M, *PREU, *PREM;
    float *QU, *QM, *BU, *BM, *CM, *CU;
    int *ROW, *CUR, *SSRC, *BSUM;
    cudaGetSymbolAddress((void**)&ZU1,   g_zu1);
    cudaGetSymbolAddress((void**)&ZM1,   g_zm1);
    cudaGetSymbolAddress((void**)&HSMU1, g_hsmu1);
    cudaGetSymbolAddress((void**)&PU,    g_Pu);
    cudaGetSymbolAddress((void**)&PM,    g_Pm);
    cudaGetSymbolAddress((void**)&S1U,   g_s1u);
    cudaGetSymbolAddress((void**)&S1M,   g_s1m);
    cudaGetSymbolAddress((void**)&PREU,  g_preu);
    cudaGetSymbolAddress((void**)&PREM,  g_prem);
    cudaGetSymbolAddress((void**)&QU,    g_Qu);
    cudaGetSymbolAddress((void**)&QM,    g_Qm);
    cudaGetSymbolAddress((void**)&BU,    g_Bu);
    cudaGetSymbolAddress((void**)&BM,    g_Bm);
    cudaGetSymbolAddress((void**)&CM,    g_cm);
    cudaGetSymbolAddress((void**)&CU,    g_cu);
    cudaGetSymbolAddress((void**)&ROW,   g_row);
    cudaGetSymbolAddress((void**)&CUR,   g_cur);
    cudaGetSymbolAddress((void**)&SSRC,  g_ssrc);
    cudaGetSymbolAddress((void**)&BSUM,  g_bsum);

    int nb = (NTOT + 1023) / 1024;

    // 1-3: CSR head
    zero_int<<<(NTOT + 255) / 256, 256>>>(CUR, NTOT);
    count2_k<<<(2 * NE + 255) / 256, 256>>>(um_dst, mu_dst, CUR);
    scan_block<<<nb, 1024>>>(CUR, ROW, BSUM, NTOT);   // also zeroes CUR

    // 4: hs GEMM (independent of CSR) — profiled by ncu -s5-c1
    {
        GP pa = { xm, w1mu_s, HSMU1, NM };
        dim3 grid(1, (NM + TBM - 1) / TBM, 1);
        gemm_dual<<<grid, 256>>>(pa, pa);
    }

    // 5-6: CSR tail
    scan_bsum<<<1, 128>>>(BSUM, nb);
    scatter2_k<<<(2 * NE + 255) / 256, 256>>>(um_src, um_dst, mu_src, mu_dst,
                                              ROW, BSUM, CUR, SSRC);

    // 7: weight compositions
    compose_all<<<(2560 + 32768 + 32 + 255) / 256, 256>>>(
        w1um_s, a1um_s, w1mu_d, a1mu_d, w1mu_s, a1mu_s, w1um_d, a1um_d,
        w2um_s, a2um_s, w2mu_d, a2mu_d, w2mu_s, a2mu_s, w2um_d, a2um_d,
        dw1, b2um, b2mu, QU, QM, BU, BM, CM, CU);

    // 8: layer-1 node scores (both types, one launch)
    score_both<<<((NU + NM) * 32 + 255) / 256, 256>>>(xu, QU, S1U, xm, QM, S1M);

    // 9: layer-1 aggregation (both directions, one launch)
    agg1_both<<<NM + NU / 2, 256>>>(xu, S1U, S1M, w1um_s, b1um, ZM1,
                                    HSMU1, b1mu, ZU1, ROW, CUR, BSUM, SSRC);

    // 10: layer-2 projections
    {
        GP p0 = { ZU1, BU, PU, NU };
        GP p1 = { ZM1, BM, PM, NM };
        dim3 grid(1, (NU + TBM - 1) / TBM, 2);
        gemm_dual<<<grid, 256>>>(p0, p1);
    }

    // 11: layer-2 aggregation fused with decoder pre (4 dst per block)
    agg2<<<NTOT / 4, 256>>>(PU, PM, CM, CU, PREM, PREU, ROW, CUR, BSUM, SSRC);

    // 12: decoder final
    dec_final<<<(NEL + 255) / 256, 256>>>(PREU, PREM, lab_u, lab_m,
                                          db1, dw2, db2, (float*)d_out, NEL);
}